// round 7
// baseline (speedup 1.0000x reference)
#include <cuda_runtime.h>
#include <cuda_fp16.h>
#include <stdint.h>

#define TT 512
#define NB 256
#define HH 256
#define GG 1024

// vcol = jj*4 + gate  (jj = hidden col; gate: 0=i 1=f 2=g 3=o)
__device__ float    g_xw[(size_t)TT * NB * GG];   // [t][n][vcol] fp32
__device__ __half   g_xh[(size_t)NB * TT * 256];  // x in fp16, rows n*T+t
__device__ __half   g_wtx[1024 * 256];            // [vcol][k] Wx fp16
__device__ __half   g_wth[1024 * 256];            // [vcol][k] Wh fp16
__device__ float    g_bvc[1024];                  // combined bias per vcol

__device__ __forceinline__ void mma16(float d[4], uint32_t a0, uint32_t a1,
                                      uint32_t a2, uint32_t a3, uint32_t b0, uint32_t b1) {
    asm volatile("mma.sync.aligned.m16n8k16.row.col.f32.f16.f16.f32 "
                 "{%0,%1,%2,%3}, {%4,%5,%6,%7}, {%8,%9}, {%0,%1,%2,%3};\n"
                 : "+f"(d[0]), "+f"(d[1]), "+f"(d[2]), "+f"(d[3])
                 : "r"(a0), "r"(a1), "r"(a2), "r"(a3), "r"(b0), "r"(b1));
}
__device__ __forceinline__ float sigm(float x) { return __fdividef(1.f, 1.f + __expf(-x)); }
__device__ __forceinline__ float tanh_acc(float x) { return 1.f - __fdividef(2.f, __expf(2.f * x) + 1.f); }
__device__ __forceinline__ uint32_t lds_u32h(const __half* p) {
    return *reinterpret_cast<const uint32_t*>(p);
}
__device__ __forceinline__ uint32_t smem_u32(const void* p) {
    return (uint32_t)__cvta_generic_to_shared(p);
}
__device__ __forceinline__ void ldsm4(uint32_t& a0, uint32_t& a1, uint32_t& a2,
                                      uint32_t& a3, uint32_t addr) {
    asm volatile("ldmatrix.sync.aligned.m8n8.x4.shared.b16 {%0,%1,%2,%3}, [%4];"
                 : "=r"(a0), "=r"(a1), "=r"(a2), "=r"(a3) : "r"(addr));
}

// ============ Prep kernels ================================================
__global__ void prep_w(const float* __restrict__ xi, const float* __restrict__ xf,
                       const float* __restrict__ xg, const float* __restrict__ xo,
                       const float* __restrict__ hi, const float* __restrict__ hf,
                       const float* __restrict__ hg, const float* __restrict__ ho) {
    int which = blockIdx.x >> 10, vv = blockIdx.x & 1023;
    int jj = vv >> 2, gt = vv & 3, k = threadIdx.x;
    const float* w;
    if (which == 0) w = (gt == 0) ? xi : (gt == 1) ? xf : (gt == 2) ? xg : xo;
    else            w = (gt == 0) ? hi : (gt == 1) ? hf : (gt == 2) ? hg : ho;
    __half* dst = which == 0 ? g_wtx : g_wth;
    dst[((size_t)vv << 8) + k] = __float2half_rn(w[k * 256 + jj]);
}
__global__ void prep_b(const float* __restrict__ b0, const float* __restrict__ b1,
                       const float* __restrict__ b2, const float* __restrict__ b3,
                       const float* __restrict__ b4, const float* __restrict__ b5,
                       const float* __restrict__ b6, const float* __restrict__ b7) {
    int vv = blockIdx.x * 256 + threadIdx.x;
    int jj = vv >> 2, gt = vv & 3;
    const float* bx = (gt == 0) ? b0 : (gt == 1) ? b2 : (gt == 2) ? b4 : b6;
    const float* bh = (gt == 0) ? b1 : (gt == 1) ? b3 : (gt == 2) ? b5 : b7;
    g_bvc[vv] = bx[jj] + bh[jj];
}
__global__ void prep_x(const float* __restrict__ x) {
    size_t i = ((size_t)blockIdx.x * 256 + threadIdx.x);   // float4 index
    float4 v = *(const float4*)(x + i * 4);
    __half2 h0 = __floats2half2_rn(v.x, v.y);
    __half2 h1 = __floats2half2_rn(v.z, v.w);
    uint2 pk; pk.x = *(uint32_t*)&h0; pk.y = *(uint32_t*)&h1;
    *(uint2*)(g_xh + i * 4) = pk;
}

// ================= Phase 1: xW(+b) in vcol order, fp16 mma =================
// grid (8, 1024): 128 rows x 128 vcols, K=256.
#define P1S 40

__global__ void __launch_bounds__(256) lstm_xw_kernel()
{
    __shared__ __align__(16) __half x_s[128 * P1S];
    __shared__ __align__(16) __half w_s[128 * P1S];

    const int tid = threadIdx.x, lane = tid & 31, warp = tid >> 5;
    const int wm = warp >> 1, wn = warp & 1;
    const int u = lane >> 2, r = lane & 3;
    const int row0 = blockIdx.y * 128;
    const int vc0 = blockIdx.x * 128;
    const __half* wt = g_wtx + (size_t)vc0 * 256;
    const __half* xt = g_xh + (size_t)row0 * 256;

    float acc[2][8][4];
    #pragma unroll
    for (int i = 0; i < 2; i++)
        #pragma unroll
        for (int j = 0; j < 8; j++)
            #pragma unroll
            for (int k = 0; k < 4; k++) acc[i][j][k] = 0.f;

    const int srow = tid >> 1, shc = (tid & 1) * 16;

    for (int k0 = 0; k0 < 256; k0 += 32) {
        {
            const __half* src = xt + (size_t)srow * 256 + k0 + shc;
            uint4 v0 = *(const uint4*)(src);
            uint4 v1 = *(const uint4*)(src + 8);
            *(uint4*)(x_s + srow * P1S + shc) = v0;
            *(uint4*)(x_s + srow * P1S + shc + 8) = v1;
        }
        {
            const __half* src = wt + (size_t)srow * 256 + k0 + shc;
            uint4 v0 = *(const uint4*)(src);
            uint4 v1 = *(const uint4*)(src + 8);
            *(uint4*)(w_s + srow * P1S + shc) = v0;
            *(uint4*)(w_s + srow * P1S + shc + 8) = v1;
        }
        __syncthreads();

        #pragma unroll
        for (int kk = 0; kk < 32; kk += 16) {
            uint32_t a[2][4];
            #pragma unroll
            for (int mt = 0; mt < 2; mt++) {
                int ar = wm * 32 + mt * 16 + u;
                const __half* p0 = x_s + ar * P1S + kk + 2 * r;
                const __half* p1 = x_s + (ar + 8) * P1S + kk + 2 * r;
                a[mt][0] = lds_u32h(p0);
                a[mt][1] = lds_u32h(p1);
                a[mt][2] = lds_u32h(p0 + 8);
                a[mt][3] = lds_u32h(p1 + 8);
            }
            #pragma unroll
            for (int nt = 0; nt < 8; nt++) {
                int bn_ = wn * 64 + nt * 8 + u;
                const __half* pb = w_s + bn_ * P1S + kk + 2 * r;
                uint32_t b0 = lds_u32h(pb);
                uint32_t b1 = lds_u32h(pb + 8);
                mma16(acc[0][nt], a[0][0], a[0][1], a[0][2], a[0][3], b0, b1);
                mma16(acc[1][nt], a[1][0], a[1][1], a[1][2], a[1][3], b0, b1);
            }
        }
        __syncthreads();
    }

    float* ebuf = (float*)x_s;
    #pragma unroll
    for (int p = 0; p < 8; p++) {
        int jcol = vc0 + wn * 64 + p * 8 + 2 * r;
        float bs0 = __ldg(g_bvc + jcol);
        float bs1 = __ldg(g_bvc + jcol + 1);
        #pragma unroll
        for (int mt = 0; mt < 2; mt++) {
            int lr = wm * 32 + mt * 16 + u;
            int lc = wn * 8 + 2 * r;
            ebuf[lr * 18 + lc]           = acc[mt][p][0] + bs0;
            ebuf[lr * 18 + lc + 1]       = acc[mt][p][1] + bs1;
            ebuf[(lr + 8) * 18 + lc]     = acc[mt][p][2] + bs0;
            ebuf[(lr + 8) * 18 + lc + 1] = acc[mt][p][3] + bs1;
        }
        __syncthreads();
        #pragma unroll
        for (int it = 0; it < 8; it++) {
            int row  = warp * 16 + it * 2 + (lane >> 4);
            int sc   = (lane >> 3) & 1;
            int col8 = lane & 7;
            int R = row0 + row;
            int t = R & (TT - 1), n = R >> 9;
            g_xw[(size_t)t * (NB * GG) + n * GG + vc0 + sc * 64 + p * 8 + col8] =
                ebuf[row * 18 + sc * 8 + col8];
        }
        __syncthreads();
    }
}

// ================= Phase 2: cluster-local recurrence =======================
// 128 CTAs = 16 clusters x 8. Cluster = one 16-row batch group.
// CTA: 16 rows x 32 hidden cols (vcols bj*128..+128). 8 warps, 16 vcols each.
// h exchange via DSMEM (st.shared::cluster) + barrier.cluster. No gmem h.
#define HSH 264

__global__ void __launch_bounds__(256, 1) __cluster_dims__(8, 1, 1)
lstm_rec_kernel(float* __restrict__ out, int out_n)
{
    __shared__ __align__(16) __half h_s[2][16 * HSH];
    __shared__ __align__(16) float  hx_s[16 * 33];

    const int tid = threadIdx.x, lane = tid & 31, warp = tid >> 5;
    const int grp = blockIdx.x >> 3, bj = blockIdx.x & 7;
    const int nBase = grp * 16, j0 = bj * 32;
    const int u = lane >> 2, r = lane & 3;

    // ---- Wh B fragments: warp covers vcols bj*128 + warp*16 + [0,16) ----
    uint32_t b0[16][2], b1[16][2];
    #pragma unroll
    for (int nt = 0; nt < 2; nt++) {
        const __half* wp = g_wth + ((size_t)(bj * 128 + warp * 16 + nt * 8 + u)) * 256;
        #pragma unroll
        for (int kc = 0; kc < 16; kc++) {
            b0[kc][nt] = *(const uint32_t*)(wp + kc * 16 + 2 * r);
            b1[kc][nt] = *(const uint32_t*)(wp + kc * 16 + 2 * r + 8);
        }
    }

    // ldmatrix lane addresses for both h buffers
    const int matrow = (lane & 7) + ((lane >> 3) & 1) * 8;
    const int colh   = (lane >> 4) * 8;
    uint32_t hsaddr[2];
    hsaddr[0] = smem_u32(&h_s[0][0]) + (matrow * HSH + colh) * 2;
    hsaddr[1] = smem_u32(&h_s[1][0]) + (matrow * HSH + colh) * 2;

    // DSMEM push addresses: warp w -> cluster rank w; lane covers row=lane>>1,
    // half=lane&1 (16 cols) at column offset j0 in the remote h buffer.
    const int prow = lane >> 1, phalf = lane & 1;
    uint32_t rbase[2];
    #pragma unroll
    for (int b = 0; b < 2; b++) {
        uint32_t la = smem_u32(&h_s[b][0]);
        uint32_t ra;
        asm("mapa.shared::cluster.u32 %0, %1, %2;" : "=r"(ra) : "r"(la), "r"(warp));
        rbase[b] = ra + (prow * HSH + j0 + phalf * 16) * 2;
    }

    // epilogue / output coords
    const int odd = lane & 1;
    const int lrow = u + (odd ? 8 : 0);
    const int myrow = nBase + lrow;
    int lcol[2];
    #pragma unroll
    for (int nt = 0; nt < 2; nt++) lcol[nt] = warp * 4 + nt * 2 + (r >> 1);

    // xw fragment pointer: rows nBase+u / +8, vcols bj*128 + warp*16 + 2r
    const float* xwp0 = g_xw + (size_t)(nBase + u) * GG + bj * 128 + warp * 16 + 2 * r;

    float cst[2] = {0.f, 0.f};

    float2 xv[2][2];
    {
        const float* p = xwp0;
        xv[0][0] = __ldg((const float2*)(p));
        xv[1][0] = __ldg((const float2*)(p + 8));
        xv[0][1] = __ldg((const float2*)(p + 8 * GG));
        xv[1][1] = __ldg((const float2*)(p + 8 * GG + 8));
    }

    for (int t = 0; t < TT; t++) {
        float acc[2][4];
        #pragma unroll
        for (int nt = 0; nt < 2; nt++) {
            acc[nt][0] = xv[nt][0].x; acc[nt][1] = xv[nt][0].y;
            acc[nt][2] = xv[nt][1].x; acc[nt][3] = xv[nt][1].y;
        }
        if (t + 1 < TT) {
            const float* p = xwp0 + (size_t)(t + 1) * (NB * GG);
            xv[0][0] = __ldg((const float2*)(p));
            xv[1][0] = __ldg((const float2*)(p + 8));
            xv[0][1] = __ldg((const float2*)(p + 8 * GG));
            xv[1][1] = __ldg((const float2*)(p + 8 * GG + 8));
        }

        if (t > 0) {
            const uint32_t ab = hsaddr[t & 1];
            #pragma unroll
            for (int kc = 0; kc < 16; kc++) {
                uint32_t a0, a1, a2, a3;
                ldsm4(a0, a1, a2, a3, ab + kc * 32);
                mma16(acc[0], a0, a1, a2, a3, b0[kc][0], b1[kc][0]);
                mma16(acc[1], a0, a1, a2, a3, b0[kc][1], b1[kc][1]);
            }
        }

        // cell update (lane-pair gate exchange)
        float hv[2];
        #pragma unroll
        for (int nt = 0; nt < 2; nt++) {
            float s0 = odd ? acc[nt][0] : acc[nt][2];
            float s1 = odd ? acc[nt][1] : acc[nt][3];
            float r0 = __shfl_xor_sync(0xFFFFFFFFu, s0, 1);
            float r1 = __shfl_xor_sync(0xFFFFFFFFu, s1, 1);
            float iv, fv, gv, ov;
            if (odd) { iv = r0; fv = r1; gv = acc[nt][2]; ov = acc[nt][3]; }
            else     { iv = acc[nt][0]; fv = acc[nt][1]; gv = r0; ov = r1; }
            float ig = sigm(iv), fg = sigm(fv), gg = tanh_acc(gv), og = sigm(ov);
            float c = fg * cst[nt] + ig * gg;
            cst[nt] = c;
            hv[nt] = og * tanh_acc(c);
        }

        if (t < TT - 1) {
            hx_s[lrow * 33 + lcol[0]] = hv[0];
            hx_s[lrow * 33 + lcol[1]] = hv[1];
            __syncthreads();
            // warp w broadcasts this CTA's 16x32 fp16 slice to rank w
            {
                const float* s = hx_s + prow * 33 + phalf * 16;
                uint32_t q[8];
                #pragma unroll
                for (int i = 0; i < 8; i++) {
                    __half2 h = __floats2half2_rn(s[2 * i], s[2 * i + 1]);
                    q[i] = *(uint32_t*)&h;
                }
                uint32_t dst = rbase[(t + 1) & 1];
                asm volatile("st.shared::cluster.v4.b32 [%0], {%1,%2,%3,%4};"
                             :: "r"(dst), "r"(q[0]), "r"(q[1]), "r"(q[2]), "r"(q[3]) : "memory");
                asm volatile("st.shared::cluster.v4.b32 [%0], {%1,%2,%3,%4};"
                             :: "r"(dst + 16), "r"(q[4]), "r"(q[5]), "r"(q[6]), "r"(q[7]) : "memory");
            }
            asm volatile("barrier.cluster.arrive.aligned;" ::: "memory");
            asm volatile("barrier.cluster.wait.aligned;" ::: "memory");
        } else {
            out[myrow * HH + j0 + lcol[0]] = hv[0];
            out[myrow * HH + j0 + lcol[1]] = hv[1];
            if (out_n >= 2 * NB * HH) {
                out[NB * HH + myrow * HH + j0 + lcol[0]] = cst[0];
                out[NB * HH + myrow * HH + j0 + lcol[1]] = cst[1];
            }
        }
    }
}

// ================= launch ==================================================
extern "C" void kernel_launch(void* const* d_in, const int* in_sizes, int n_in,
                              void* d_out, int out_size) {
    const float* x    = (const float*)d_in[0];
    const float* w_ii = (const float*)d_in[1];
    const float* w_hi = (const float*)d_in[2];
    const float* w_if = (const float*)d_in[3];
    const float* w_hf = (const float*)d_in[4];
    const float* w_ig = (const float*)d_in[5];
    const float* w_hg = (const float*)d_in[6];
    const float* w_io = (const float*)d_in[7];
    const float* w_ho = (const float*)d_in[8];
    const float* b_ii = (const float*)d_in[9];
    const float* b_hi = (const float*)d_in[10];
    const float* b_if = (const float*)d_in[11];
    const float* b_hf = (const float*)d_in[12];
    const float* b_ig = (const float*)d_in[13];
    const float* b_hg = (const float*)d_in[14];
    const float* b_io = (const float*)d_in[15];
    const float* b_ho = (const float*)d_in[16];
    float* out = (float*)d_out;

    prep_w<<<2048, 256>>>(w_ii, w_if, w_ig, w_io, w_hi, w_hf, w_hg, w_ho);
    prep_b<<<4, 256>>>(b_ii, b_hi, b_if, b_hf, b_ig, b_hg, b_io, b_ho);
    prep_x<<<(NB * TT * 256 / 4) / 256, 256>>>(x);

    dim3 g1(8, 1024);
    lstm_xw_kernel<<<g1, 256>>>();

    lstm_rec_kernel<<<128, 256>>>(out, out_size);
}

// round 8
// speedup vs baseline: 1.1317x; 1.1317x over previous
#include <cuda_runtime.h>
#include <cuda_fp16.h>
#include <stdint.h>

#define TT 512
#define NB 256
#define HH 256
#define GG 1024

// vcol = jj*4 + gate  (jj = hidden col; gate: 0=i 1=f 2=g 3=o)
__device__ float    g_xw[(size_t)TT * NB * GG];   // [t][n][vcol] fp32
__device__ __half   g_xh[(size_t)NB * TT * 256];  // x in fp16
__device__ __half   g_hh[2 * NB * HH];            // fp16 hidden, double buffered
__device__ __half   g_wtx[1024 * 256];            // [vcol][k] Wx fp16
__device__ __half   g_wth[1024 * 256];            // [vcol][k] Wh fp16
__device__ float    g_bvc[1024];                  // combined bias per vcol
__device__ unsigned g_bars[8 * 32];

__device__ __forceinline__ void mma16(float d[4], uint32_t a0, uint32_t a1,
                                      uint32_t a2, uint32_t a3, uint32_t b0, uint32_t b1) {
    asm volatile("mma.sync.aligned.m16n8k16.row.col.f32.f16.f16.f32 "
                 "{%0,%1,%2,%3}, {%4,%5,%6,%7}, {%8,%9}, {%0,%1,%2,%3};\n"
                 : "+f"(d[0]), "+f"(d[1]), "+f"(d[2]), "+f"(d[3])
                 : "r"(a0), "r"(a1), "r"(a2), "r"(a3), "r"(b0), "r"(b1));
}
__device__ __forceinline__ float sigm(float x) { return __fdividef(1.f, 1.f + __expf(-x)); }
__device__ __forceinline__ float tanh_acc(float x) { return 1.f - __fdividef(2.f, __expf(2.f * x) + 1.f); }
__device__ __forceinline__ unsigned ld_acq(const unsigned* p) {
    unsigned v; asm volatile("ld.acquire.gpu.global.u32 %0, [%1];" : "=r"(v) : "l"(p)); return v;
}
__device__ __forceinline__ void red_rel(unsigned* p, unsigned v) {
    asm volatile("red.release.gpu.global.add.u32 [%0], %1;" :: "l"(p), "r"(v) : "memory");
}
__device__ __forceinline__ uint32_t smem_u32(const void* p) {
    return (uint32_t)__cvta_generic_to_shared(p);
}
__device__ __forceinline__ void ldsm4(uint32_t& a0, uint32_t& a1, uint32_t& a2,
                                      uint32_t& a3, uint32_t addr) {
    asm volatile("ldmatrix.sync.aligned.m8n8.x4.shared.b16 {%0,%1,%2,%3}, [%4];"
                 : "=r"(a0), "=r"(a1), "=r"(a2), "=r"(a3) : "r"(addr));
}

// ============ Prep kernels ================================================
__global__ void prep_w(const float* __restrict__ xi, const float* __restrict__ xf,
                       const float* __restrict__ xg, const float* __restrict__ xo,
                       const float* __restrict__ hi, const float* __restrict__ hf,
                       const float* __restrict__ hg, const float* __restrict__ ho) {
    int which = blockIdx.x >> 10, vv = blockIdx.x & 1023;
    int jj = vv >> 2, gt = vv & 3, k = threadIdx.x;
    const float* w;
    if (which == 0) w = (gt == 0) ? xi : (gt == 1) ? xf : (gt == 2) ? xg : xo;
    else            w = (gt == 0) ? hi : (gt == 1) ? hf : (gt == 2) ? hg : ho;
    __half* dst = which == 0 ? g_wtx : g_wth;
    dst[((size_t)vv << 8) + k] = __float2half_rn(w[k * 256 + jj]);
}
__global__ void prep_b(const float* __restrict__ b0, const float* __restrict__ b1,
                       const float* __restrict__ b2, const float* __restrict__ b3,
                       const float* __restrict__ b4, const float* __restrict__ b5,
                       const float* __restrict__ b6, const float* __restrict__ b7) {
    int vv = blockIdx.x * 256 + threadIdx.x;
    int jj = vv >> 2, gt = vv & 3;
    const float* bx = (gt == 0) ? b0 : (gt == 1) ? b2 : (gt == 2) ? b4 : b6;
    const float* bh = (gt == 0) ? b1 : (gt == 1) ? b3 : (gt == 2) ? b5 : b7;
    g_bvc[vv] = bx[jj] + bh[jj];
}
__global__ void prep_x(const float* __restrict__ x) {
    size_t i = ((size_t)blockIdx.x * 256 + threadIdx.x);
    float4 v = *(const float4*)(x + i * 4);
    __half2 h0 = __floats2half2_rn(v.x, v.y);
    __half2 h1 = __floats2half2_rn(v.z, v.w);
    uint2 pk; pk.x = *(uint32_t*)&h0; pk.y = *(uint32_t*)&h1;
    *(uint2*)(g_xh + i * 4) = pk;
}

// ================= Phase 1: xW(+b), ldmatrix + resident B =================
// grid (8, 1024): 128 rows x 128 vcols, K=256. B (Wx slice) resident in smem.
#define P1XS 40    // x_s row stride (halves)
#define P1WS 264   // w_s row stride (halves)
#define P1_SMEM ((128 * P1WS + 128 * P1XS) * 2)

__global__ void __launch_bounds__(256) lstm_xw_kernel()
{
    extern __shared__ __align__(16) __half sm1[];
    __half* w_s = sm1;                      // [128][264]
    __half* x_s = sm1 + 128 * P1WS;         // [128][40]

    const int tid = threadIdx.x, lane = tid & 31, warp = tid >> 5;
    const int wm = warp >> 1, wn = warp & 1;
    const int u = lane >> 2, r = lane & 3;
    const int row0 = blockIdx.y * 128;
    const int vc0 = blockIdx.x * 128;
    const __half* wt = g_wtx + (size_t)vc0 * 256;
    const __half* xt = g_xh + (size_t)row0 * 256;

    // ---- stage full B tile 128 x 256 once ----
    #pragma unroll
    for (int i = 0; i < 16; i++) {
        int q = i * 256 + tid;              // uint4 (8-half) chunk id, 4096 total
        int rw = q >> 5, c8 = (q & 31) << 3;
        *(uint4*)(w_s + rw * P1WS + c8) = *(const uint4*)(wt + (size_t)rw * 256 + c8);
    }

    // ldmatrix lane address components
    const int matrow = (lane & 7) + ((lane >> 3) & 1) * 8;
    const int colh   = (lane >> 4) * 8;
    const int m_id   = lane >> 3;           // 0..3 for B addressing
    // A base addrs (per mt), in x_s
    uint32_t aab[2];
    #pragma unroll
    for (int mt = 0; mt < 2; mt++)
        aab[mt] = smem_u32(x_s) + ((wm * 32 + mt * 16 + matrow) * P1XS + colh) * 2;
    // B base addrs (per nt-pair p), in w_s: mats (nt offset m>>1, ksub m&1)
    uint32_t bb[4];
    #pragma unroll
    for (int p = 0; p < 4; p++) {
        int rowv = wn * 64 + (p * 2 + (m_id >> 1)) * 8 + (lane & 7);
        bb[p] = smem_u32(w_s) + (rowv * P1WS + (m_id & 1) * 8) * 2;
    }

    float acc[2][8][4];
    #pragma unroll
    for (int i = 0; i < 2; i++)
        #pragma unroll
        for (int j = 0; j < 8; j++)
            #pragma unroll
            for (int k = 0; k < 4; k++) acc[i][j][k] = 0.f;

    const int srow = tid >> 1, shc = (tid & 1) * 16;

    for (int k0 = 0; k0 < 256; k0 += 32) {
        // stage x tile 128 x 32
        {
            const __half* src = xt + (size_t)srow * 256 + k0 + shc;
            uint4 v0 = *(const uint4*)(src);
            uint4 v1 = *(const uint4*)(src + 8);
            *(uint4*)(x_s + srow * P1XS + shc) = v0;
            *(uint4*)(x_s + srow * P1XS + shc + 8) = v1;
        }
        __syncthreads();

        #pragma unroll
        for (int kk = 0; kk < 32; kk += 16) {
            uint32_t a[2][4];
            ldsm4(a[0][0], a[0][1], a[0][2], a[0][3], aab[0] + kk * 2);
            ldsm4(a[1][0], a[1][1], a[1][2], a[1][3], aab[1] + kk * 2);
            #pragma unroll
            for (int p = 0; p < 4; p++) {
                uint32_t b00, b01, b10, b11;   // {b0[nt0],b1[nt0],b0[nt1],b1[nt1]}
                ldsm4(b00, b01, b10, b11, bb[p] + (k0 + kk) * 2);
                mma16(acc[0][2 * p],     a[0][0], a[0][1], a[0][2], a[0][3], b00, b01);
                mma16(acc[1][2 * p],     a[1][0], a[1][1], a[1][2], a[1][3], b00, b01);
                mma16(acc[0][2 * p + 1], a[0][0], a[0][1], a[0][2], a[0][3], b10, b11);
                mma16(acc[1][2 * p + 1], a[1][0], a[1][1], a[1][2], a[1][3], b10, b11);
            }
        }
        __syncthreads();
    }

    // ---- epilogue: stage through smem, coalesced 32B strips ----
    float* ebuf = (float*)x_s;
    #pragma unroll
    for (int p = 0; p < 8; p++) {
        int jcol = vc0 + wn * 64 + p * 8 + 2 * r;
        float bs0 = __ldg(g_bvc + jcol);
        float bs1 = __ldg(g_bvc + jcol + 1);
        #pragma unroll
        for (int mt = 0; mt < 2; mt++) {
            int lr = wm * 32 + mt * 16 + u;
            int lc = wn * 8 + 2 * r;
            ebuf[lr * 18 + lc]           = acc[mt][p][0] + bs0;
            ebuf[lr * 18 + lc + 1]       = acc[mt][p][1] + bs1;
            ebuf[(lr + 8) * 18 + lc]     = acc[mt][p][2] + bs0;
            ebuf[(lr + 8) * 18 + lc + 1] = acc[mt][p][3] + bs1;
        }
        __syncthreads();
        #pragma unroll
        for (int it = 0; it < 8; it++) {
            int row  = warp * 16 + it * 2 + (lane >> 4);
            int sc   = (lane >> 3) & 1;
            int col8 = lane & 7;
            int R = row0 + row;
            int t = R & (TT - 1), n = R >> 9;
            g_xw[(size_t)t * (NB * GG) + n * GG + vc0 + sc * 64 + p * 8 + col8] =
                ebuf[row * 18 + sc * 8 + col8];
        }
        __syncthreads();
    }
}

// ================= Phase 2: persistent recurrence (R6 + ldmatrix) =========
#define HSH 264

__global__ void __launch_bounds__(256, 1) lstm_rec_kernel(
    float* __restrict__ out, int out_n)
{
    __shared__ __align__(16) __half h_s[32 * HSH];
    __shared__ __align__(16) float  hx_s[32 * 16];

    const int tid = threadIdx.x, lane = tid & 31, warp = tid >> 5;
    const int wm = warp & 1, wc = warp >> 1;
    const int bn = blockIdx.x >> 4, bj = blockIdx.x & 15;
    const int nBase = bn * 32, j0 = bj * 16;
    const int u = lane >> 2, r = lane & 3;
    const int rA = wm * 16 + u;

    unsigned* bar = &g_bars[bn * 32];

    // Wh B fragments (persistent, vcol-contiguous rows)
    uint32_t b0[16][2], b1[16][2];
    #pragma unroll
    for (int nt = 0; nt < 2; nt++) {
        const __half* wp = g_wth + ((size_t)(bj * 64 + wc * 16 + nt * 8 + u)) * 256;
        #pragma unroll
        for (int kc = 0; kc < 16; kc++) {
            b0[kc][nt] = *(const uint32_t*)(wp + kc * 16 + 2 * r);
            b1[kc][nt] = *(const uint32_t*)(wp + kc * 16 + 2 * r + 8);
        }
    }

    // ldmatrix A base address (rows wm*16 .. +15)
    const int matrow = (lane & 7) + ((lane >> 3) & 1) * 8;
    const int colh   = (lane >> 4) * 8;
    const uint32_t habase = smem_u32(h_s) + ((wm * 16 + matrow) * HSH + colh) * 2;

    const int odd = lane & 1;
    const int lrow = rA + (odd ? 8 : 0);
    const int myrow = nBase + lrow;
    int lcol[2];
    #pragma unroll
    for (int nt = 0; nt < 2; nt++) lcol[nt] = wc * 4 + nt * 2 + (r >> 1);

    const float* xwp0 = g_xw + (size_t)(nBase + rA) * GG + bj * 64 + wc * 16 + 2 * r;

    float cst[2] = {0.f, 0.f};

    float2 xv[2][2];
    {
        const float* p = xwp0;
        xv[0][0] = __ldg((const float2*)(p));
        xv[1][0] = __ldg((const float2*)(p + 8));
        xv[0][1] = __ldg((const float2*)(p + 8 * GG));
        xv[1][1] = __ldg((const float2*)(p + 8 * GG + 8));
    }

    for (int t = 0; t < TT; t++) {
        float acc[2][4];
        #pragma unroll
        for (int nt = 0; nt < 2; nt++) {
            acc[nt][0] = xv[nt][0].x; acc[nt][1] = xv[nt][0].y;
            acc[nt][2] = xv[nt][1].x; acc[nt][3] = xv[nt][1].y;
        }
        if (t + 1 < TT) {
            const float* p = xwp0 + (size_t)(t + 1) * (NB * GG);
            xv[0][0] = __ldg((const float2*)(p));
            xv[1][0] = __ldg((const float2*)(p + 8));
            xv[0][1] = __ldg((const float2*)(p + 8 * GG));
            xv[1][1] = __ldg((const float2*)(p + 8 * GG + 8));
        }

        if (t > 0) {
            if (tid == 0) {
                unsigned target = 16u * (unsigned)t;
                while (ld_acq(bar) < target) { }
            }
            __syncthreads();
            const __half* hsrc = g_hh + (t & 1) * (NB * HH) + nBase * HH;
            #pragma unroll
            for (int i = 0; i < 4; i++) {
                int f = i * 256 + tid, row = f >> 5, c8 = (f & 31) << 3;
                uint4 v = __ldcg((const uint4*)(hsrc + row * HH + c8));
                *(uint4*)(h_s + row * HSH + c8) = v;
            }
            __syncthreads();

            #pragma unroll
            for (int kc = 0; kc < 16; kc++) {
                uint32_t a0, a1, a2, a3;
                ldsm4(a0, a1, a2, a3, habase + kc * 32);
                mma16(acc[0], a0, a1, a2, a3, b0[kc][0], b1[kc][0]);
                mma16(acc[1], a0, a1, a2, a3, b0[kc][1], b1[kc][1]);
            }
        }

        float hv[2];
        #pragma unroll
        for (int nt = 0; nt < 2; nt++) {
            float s0 = odd ? acc[nt][0] : acc[nt][2];
            float s1 = odd ? acc[nt][1] : acc[nt][3];
            float r0 = __shfl_xor_sync(0xFFFFFFFFu, s0, 1);
            float r1 = __shfl_xor_sync(0xFFFFFFFFu, s1, 1);
            float iv, fv, gv, ov;
            if (odd) { iv = r0; fv = r1; gv = acc[nt][2]; ov = acc[nt][3]; }
            else     { iv = acc[nt][0]; fv = acc[nt][1]; gv = r0; ov = r1; }
            float ig = sigm(iv), fg = sigm(fv), gg = tanh_acc(gv), og = sigm(ov);
            float c = fg * cst[nt] + ig * gg;
            cst[nt] = c;
            hv[nt] = og * tanh_acc(c);
        }

        if (t < TT - 1) {
            hx_s[lrow * 16 + lcol[0]] = hv[0];
            hx_s[lrow * 16 + lcol[1]] = hv[1];
            __syncthreads();
            if (tid < 64) {
                int row = tid >> 1, part = tid & 1;
                const float* s = hx_s + row * 16 + part * 8;
                __half2 h0 = __floats2half2_rn(s[0], s[1]);
                __half2 h1 = __floats2half2_rn(s[2], s[3]);
                __half2 h2 = __floats2half2_rn(s[4], s[5]);
                __half2 h3 = __floats2half2_rn(s[6], s[7]);
                uint4 pk;
                pk.x = *(uint32_t*)&h0; pk.y = *(uint32_t*)&h1;
                pk.z = *(uint32_t*)&h2; pk.w = *(uint32_t*)&h3;
                __half* hdst = g_hh + ((t + 1) & 1) * (NB * HH)
                             + (nBase + row) * HH + j0 + part * 8;
                __stcg((uint4*)hdst, pk);
            }
            __syncthreads();
            if (tid == 0) red_rel(bar, 1u);
        } else {
            out[myrow * HH + j0 + lcol[0]] = hv[0];
            out[myrow * HH + j0 + lcol[1]] = hv[1];
            if (out_n >= 2 * NB * HH) {
                out[NB * HH + myrow * HH + j0 + lcol[0]] = cst[0];
                out[NB * HH + myrow * HH + j0 + lcol[1]] = cst[1];
            }
        }
    }
}

// ================= launch ==================================================
extern "C" void kernel_launch(void* const* d_in, const int* in_sizes, int n_in,
                              void* d_out, int out_size) {
    const float* x    = (const float*)d_in[0];
    const float* w_ii = (const float*)d_in[1];
    const float* w_hi = (const float*)d_in[2];
    const float* w_if = (const float*)d_in[3];
    const float* w_hf = (const float*)d_in[4];
    const float* w_ig = (const float*)d_in[5];
    const float* w_hg = (const float*)d_in[6];
    const float* w_io = (const float*)d_in[7];
    const float* w_ho = (const float*)d_in[8];
    const float* b_ii = (const float*)d_in[9];
    const float* b_hi = (const float*)d_in[10];
    const float* b_if = (const float*)d_in[11];
    const float* b_hf = (const float*)d_in[12];
    const float* b_ig = (const float*)d_in[13];
    const float* b_hg = (const float*)d_in[14];
    const float* b_io = (const float*)d_in[15];
    const float* b_ho = (const float*)d_in[16];
    float* out = (float*)d_out;

    void* barAddr = nullptr;
    cudaGetSymbolAddress(&barAddr, g_bars);
    cudaMemsetAsync(barAddr, 0, 8 * 32 * sizeof(unsigned), 0);

    prep_w<<<2048, 256>>>(w_ii, w_if, w_ig, w_io, w_hi, w_hf, w_hg, w_ho);
    prep_b<<<4, 256>>>(b_ii, b_hi, b_if, b_hf, b_ig, b_hg, b_io, b_ho);
    prep_x<<<(NB * TT * 256 / 4) / 256, 256>>>(x);

    static int smem_set = 0;
    if (!smem_set) {
        cudaFuncSetAttribute(lstm_xw_kernel,
                             cudaFuncAttributeMaxDynamicSharedMemorySize, P1_SMEM);
        smem_set = 1;
    }
    dim3 g1(8, 1024);
    lstm_xw_kernel<<<g1, 256, P1_SMEM>>>();

    lstm_rec_kernel<<<128, 256>>>(out, out_size);
}

// round 9
// speedup vs baseline: 1.1935x; 1.0546x over previous
#include <cuda_runtime.h>
#include <cuda_fp16.h>
#include <stdint.h>

#define TT 512
#define NB 256
#define HH 256
#define GG 1024

// vcol = jj*4 + gate  (jj = hidden col; gate: 0=i 1=f 2=g 3=o)
__device__ __half   g_xwh[(size_t)TT * NB * GG];  // [t][n][vcol] fp16
__device__ __half   g_xh[(size_t)NB * TT * 256];  // x in fp16
__device__ __half   g_hh[2 * NB * HH];            // fp16 hidden, double buffered
__device__ __half   g_wtx[1024 * 256];            // [vcol][k] Wx fp16
__device__ __half   g_wth[1024 * 256];            // [vcol][k] Wh fp16
__device__ float    g_bvc[1024];                  // combined bias per vcol
__device__ unsigned g_bars[8 * 32];

__device__ __forceinline__ void mma16(float d[4], uint32_t a0, uint32_t a1,
                                      uint32_t a2, uint32_t a3, uint32_t b0, uint32_t b1) {
    asm volatile("mma.sync.aligned.m16n8k16.row.col.f32.f16.f16.f32 "
                 "{%0,%1,%2,%3}, {%4,%5,%6,%7}, {%8,%9}, {%0,%1,%2,%3};\n"
                 : "+f"(d[0]), "+f"(d[1]), "+f"(d[2]), "+f"(d[3])
                 : "r"(a0), "r"(a1), "r"(a2), "r"(a3), "r"(b0), "r"(b1));
}
__device__ __forceinline__ float sigm(float x) { return __fdividef(1.f, 1.f + __expf(-x)); }
__device__ __forceinline__ float tanh_acc(float x) { return 1.f - __fdividef(2.f, __expf(2.f * x) + 1.f); }
__device__ __forceinline__ unsigned ld_acq(const unsigned* p) {
    unsigned v; asm volatile("ld.acquire.gpu.global.u32 %0, [%1];" : "=r"(v) : "l"(p)); return v;
}
__device__ __forceinline__ void red_rel(unsigned* p, unsigned v) {
    asm volatile("red.release.gpu.global.add.u32 [%0], %1;" :: "l"(p), "r"(v) : "memory");
}
__device__ __forceinline__ uint32_t smem_u32(const void* p) {
    return (uint32_t)__cvta_generic_to_shared(p);
}
__device__ __forceinline__ void ldsm4(uint32_t& a0, uint32_t& a1, uint32_t& a2,
                                      uint32_t& a3, uint32_t addr) {
    asm volatile("ldmatrix.sync.aligned.m8n8.x4.shared.b16 {%0,%1,%2,%3}, [%4];"
                 : "=r"(a0), "=r"(a1), "=r"(a2), "=r"(a3) : "r"(addr));
}
__device__ __forceinline__ void cp16(uint32_t dst, const void* src) {
    asm volatile("cp.async.cg.shared.global [%0], [%1], 16;" :: "r"(dst), "l"(src));
}

// ============ Prep kernels ================================================
__global__ void prep_w(const float* __restrict__ xi, const float* __restrict__ xf,
                       const float* __restrict__ xg, const float* __restrict__ xo,
                       const float* __restrict__ hi, const float* __restrict__ hf,
                       const float* __restrict__ hg, const float* __restrict__ ho) {
    int which = blockIdx.x >> 10, vv = blockIdx.x & 1023;
    int jj = vv >> 2, gt = vv & 3, k = threadIdx.x;
    const float* w;
    if (which == 0) w = (gt == 0) ? xi : (gt == 1) ? xf : (gt == 2) ? xg : xo;
    else            w = (gt == 0) ? hi : (gt == 1) ? hf : (gt == 2) ? hg : ho;
    __half* dst = which == 0 ? g_wtx : g_wth;
    dst[((size_t)vv << 8) + k] = __float2half_rn(w[k * 256 + jj]);
}
__global__ void prep_b(const float* __restrict__ b0, const float* __restrict__ b1,
                       const float* __restrict__ b2, const float* __restrict__ b3,
                       const float* __restrict__ b4, const float* __restrict__ b5,
                       const float* __restrict__ b6, const float* __restrict__ b7) {
    int vv = blockIdx.x * 256 + threadIdx.x;
    int jj = vv >> 2, gt = vv & 3;
    const float* bx = (gt == 0) ? b0 : (gt == 1) ? b2 : (gt == 2) ? b4 : b6;
    const float* bh = (gt == 0) ? b1 : (gt == 1) ? b3 : (gt == 2) ? b5 : b7;
    g_bvc[vv] = bx[jj] + bh[jj];
}
__global__ void prep_x(const float* __restrict__ x) {
    size_t i = ((size_t)blockIdx.x * 256 + threadIdx.x);
    float4 v = *(const float4*)(x + i * 4);
    __half2 h0 = __floats2half2_rn(v.x, v.y);
    __half2 h1 = __floats2half2_rn(v.z, v.w);
    uint2 pk; pk.x = *(uint32_t*)&h0; pk.y = *(uint32_t*)&h1;
    *(uint2*)(g_xh + i * 4) = pk;
}

// ================= Phase 1: xW(+b) -> fp16, 64x64 warp tiles ==============
// grid (8, 512): 256 rows x 128 vcols, K=256. B resident; x double-buffered
// via cp.async. 8 warps: wm=warp>>1 (64 rows), wn=warp&1 (64 vcols).
#define P1XS 40
#define P1WS 264
#define P1_SMEM ((128 * P1WS + 2 * 256 * P1XS) * 2)

__global__ void __launch_bounds__(256) lstm_xw_kernel()
{
    extern __shared__ __align__(16) __half sm1[];
    __half* w_s = sm1;                         // [128][264]
    __half* x_s[2] = { sm1 + 128 * P1WS,       // [256][40] x2
                       sm1 + 128 * P1WS + 256 * P1XS };

    const int tid = threadIdx.x, lane = tid & 31, warp = tid >> 5;
    const int wm = warp >> 1, wn = warp & 1;
    const int u = lane >> 2, r = lane & 3;
    const int row0 = blockIdx.y * 256;
    const int vc0 = blockIdx.x * 128;
    const __half* wt = g_wtx + (size_t)vc0 * 256;
    const __half* xt = g_xh + (size_t)row0 * 256;

    // stage resident B tile 128 x 256
    #pragma unroll
    for (int i = 0; i < 16; i++) {
        int q = i * 256 + tid;
        int rw = q >> 5, c8 = (q & 31) << 3;
        *(uint4*)(w_s + rw * P1WS + c8) = *(const uint4*)(wt + (size_t)rw * 256 + c8);
    }

    // ldmatrix lane components
    const int matrow = (lane & 7) + ((lane >> 3) & 1) * 8;
    const int colh   = (lane >> 4) * 8;
    const int m_id   = lane >> 3;
    uint32_t aab[2][4];
    #pragma unroll
    for (int b = 0; b < 2; b++)
        #pragma unroll
        for (int mt = 0; mt < 4; mt++)
            aab[b][mt] = smem_u32(x_s[b]) + ((wm * 64 + mt * 16 + matrow) * P1XS + colh) * 2;
    uint32_t bb[4];
    #pragma unroll
    for (int p = 0; p < 4; p++) {
        int rowv = wn * 64 + (p * 2 + (m_id >> 1)) * 8 + (lane & 7);
        bb[p] = smem_u32(w_s) + (rowv * P1WS + (m_id & 1) * 8) * 2;
    }

    float acc[4][8][4];
    #pragma unroll
    for (int i = 0; i < 4; i++)
        #pragma unroll
        for (int j = 0; j < 8; j++)
            #pragma unroll
            for (int k = 0; k < 4; k++) acc[i][j][k] = 0.f;

    // x staging coords: 4 x 16B per thread per k0-chunk
    int srow[4], sc8[4];
    #pragma unroll
    for (int i = 0; i < 4; i++) {
        int q = i * 256 + tid;
        srow[i] = q >> 2; sc8[i] = (q & 3) << 3;
    }

    // prime stage 0
    #pragma unroll
    for (int i = 0; i < 4; i++)
        cp16(smem_u32(x_s[0]) + (srow[i] * P1XS + sc8[i]) * 2,
             xt + (size_t)srow[i] * 256 + sc8[i]);
    asm volatile("cp.async.commit_group;");

    #pragma unroll
    for (int kc0 = 0; kc0 < 8; kc0++) {
        if (kc0 + 1 < 8) {
            const int nb = (kc0 + 1) & 1;
            #pragma unroll
            for (int i = 0; i < 4; i++)
                cp16(smem_u32(x_s[nb]) + (srow[i] * P1XS + sc8[i]) * 2,
                     xt + (size_t)srow[i] * 256 + (kc0 + 1) * 32 + sc8[i]);
            asm volatile("cp.async.commit_group;");
            asm volatile("cp.async.wait_group 1;");
        } else {
            asm volatile("cp.async.wait_group 0;");
        }
        __syncthreads();

        const int cb = kc0 & 1;
        #pragma unroll
        for (int kk = 0; kk < 32; kk += 16) {
            uint32_t a[4][4];
            #pragma unroll
            for (int mt = 0; mt < 4; mt++)
                ldsm4(a[mt][0], a[mt][1], a[mt][2], a[mt][3], aab[cb][mt] + kk * 2);
            #pragma unroll
            for (int p = 0; p < 4; p++) {
                uint32_t b00, b01, b10, b11;
                ldsm4(b00, b01, b10, b11, bb[p] + (kc0 * 32 + kk) * 2);
                #pragma unroll
                for (int mt = 0; mt < 4; mt++) {
                    mma16(acc[mt][2 * p],     a[mt][0], a[mt][1], a[mt][2], a[mt][3], b00, b01);
                    mma16(acc[mt][2 * p + 1], a[mt][0], a[mt][1], a[mt][2], a[mt][3], b10, b11);
                }
            }
        }
        __syncthreads();
    }

    // epilogue: direct fp16 half2 stores
    #pragma unroll
    for (int p = 0; p < 8; p++) {
        int jcol = vc0 + wn * 64 + p * 8 + 2 * r;
        float bs0 = __ldg(g_bvc + jcol);
        float bs1 = __ldg(g_bvc + jcol + 1);
        #pragma unroll
        for (int mt = 0; mt < 4; mt++) {
            int R1 = row0 + wm * 64 + mt * 16 + u;
            int R2 = R1 + 8;
            int t1 = R1 & (TT - 1), n1 = R1 >> 9;
            int t2 = R2 & (TT - 1), n2 = R2 >> 9;
            __half2 hA = __floats2half2_rn(acc[mt][p][0] + bs0, acc[mt][p][1] + bs1);
            __half2 hB = __floats2half2_rn(acc[mt][p][2] + bs0, acc[mt][p][3] + bs1);
            *(uint32_t*)(g_xwh + (size_t)t1 * (NB * GG) + n1 * GG + jcol) = *(uint32_t*)&hA;
            *(uint32_t*)(g_xwh + (size_t)t2 * (NB * GG) + n2 * GG + jcol) = *(uint32_t*)&hB;
        }
    }
}

// ================= Phase 2: persistent recurrence ==========================
#define HSH 264

__global__ void __launch_bounds__(256, 1) lstm_rec_kernel(
    float* __restrict__ out, int out_n)
{
    __shared__ __align__(16) __half h_s[32 * HSH];
    __shared__ __align__(16) float  hx_s[32 * 16];

    const int tid = threadIdx.x, lane = tid & 31, warp = tid >> 5;
    const int wm = warp & 1, wc = warp >> 1;
    const int bn = blockIdx.x >> 4, bj = blockIdx.x & 15;
    const int nBase = bn * 32, j0 = bj * 16;
    const int u = lane >> 2, r = lane & 3;
    const int rA = wm * 16 + u;

    unsigned* bar = &g_bars[bn * 32];

    // Wh B fragments (persistent)
    uint32_t b0[16][2], b1[16][2];
    #pragma unroll
    for (int nt = 0; nt < 2; nt++) {
        const __half* wp = g_wth + ((size_t)(bj * 64 + wc * 16 + nt * 8 + u)) * 256;
        #pragma unroll
        for (int kc = 0; kc < 16; kc++) {
            b0[kc][nt] = *(const uint32_t*)(wp + kc * 16 + 2 * r);
            b1[kc][nt] = *(const uint32_t*)(wp + kc * 16 + 2 * r + 8);
        }
    }

    const int matrow = (lane & 7) + ((lane >> 3) & 1) * 8;
    const int colh   = (lane >> 4) * 8;
    const uint32_t habase = smem_u32(h_s) + ((wm * 16 + matrow) * HSH + colh) * 2;

    const int odd = lane & 1;
    const int lrow = rA + (odd ? 8 : 0);
    const int myrow = nBase + lrow;
    int lcol[2];
    #pragma unroll
    for (int nt = 0; nt < 2; nt++) lcol[nt] = wc * 4 + nt * 2 + (r >> 1);

    const __half* xwp0 = g_xwh + (size_t)(nBase + rA) * GG + bj * 64 + wc * 16 + 2 * r;

    float cst[2] = {0.f, 0.f};

    uint32_t xv[4];   // half2 x4: [nt0 rowA, nt1 rowA, nt0 rowB, nt1 rowB]
    {
        const __half* p = xwp0;
        xv[0] = *(const uint32_t*)(p);
        xv[1] = *(const uint32_t*)(p + 8);
        xv[2] = *(const uint32_t*)(p + 8 * GG);
        xv[3] = *(const uint32_t*)(p + 8 * GG + 8);
    }

    for (int t = 0; t < TT; t++) {
        float acc[2][4], acb[2][4];
        #pragma unroll
        for (int nt = 0; nt < 2; nt++) {
            float2 fa = __half22float2(*(__half2*)&xv[nt]);
            float2 fb = __half22float2(*(__half2*)&xv[nt + 2]);
            acc[nt][0] = fa.x; acc[nt][1] = fa.y;
            acc[nt][2] = fb.x; acc[nt][3] = fb.y;
            acb[nt][0] = 0.f; acb[nt][1] = 0.f; acb[nt][2] = 0.f; acb[nt][3] = 0.f;
        }
        if (t + 1 < TT) {
            const __half* p = xwp0 + (size_t)(t + 1) * (NB * GG);
            xv[0] = __ldg((const uint32_t*)(p));
            xv[1] = __ldg((const uint32_t*)(p + 8));
            xv[2] = __ldg((const uint32_t*)(p + 8 * GG));
            xv[3] = __ldg((const uint32_t*)(p + 8 * GG + 8));
        }

        if (t > 0) {
            if (tid == 0) {
                unsigned target = 16u * (unsigned)t;
                while (ld_acq(bar) < target) { }
            }
            __syncthreads();
            const __half* hsrc = g_hh + (t & 1) * (NB * HH) + nBase * HH;
            #pragma unroll
            for (int i = 0; i < 4; i++) {
                int f = i * 256 + tid, row = f >> 5, c8 = (f & 31) << 3;
                uint4 v = __ldcg((const uint4*)(hsrc + row * HH + c8));
                *(uint4*)(h_s + row * HSH + c8) = v;
            }
            __syncthreads();

            // split-K: two independent accumulation chains
            #pragma unroll
            for (int kc = 0; kc < 8; kc++) {
                uint32_t a0, a1, a2, a3, c0, c1, c2, c3;
                ldsm4(a0, a1, a2, a3, habase + kc * 32);
                ldsm4(c0, c1, c2, c3, habase + (kc + 8) * 32);
                mma16(acc[0], a0, a1, a2, a3, b0[kc][0], b1[kc][0]);
                mma16(acc[1], a0, a1, a2, a3, b0[kc][1], b1[kc][1]);
                mma16(acb[0], c0, c1, c2, c3, b0[kc + 8][0], b1[kc + 8][0]);
                mma16(acb[1], c0, c1, c2, c3, b0[kc + 8][1], b1[kc + 8][1]);
            }
            #pragma unroll
            for (int nt = 0; nt < 2; nt++)
                #pragma unroll
                for (int j = 0; j < 4; j++) acc[nt][j] += acb[nt][j];
        }

        float hv[2];
        #pragma unroll
        for (int nt = 0; nt < 2; nt++) {
            float s0 = odd ? acc[nt][0] : acc[nt][2];
            float s1 = odd ? acc[nt][1] : acc[nt][3];
            float r0 = __shfl_xor_sync(0xFFFFFFFFu, s0, 1);
            float r1 = __shfl_xor_sync(0xFFFFFFFFu, s1, 1);
            float iv, fv, gv, ov;
            if (odd) { iv = r0; fv = r1; gv = acc[nt][2]; ov = acc[nt][3]; }
            else     { iv = acc[nt][0]; fv = acc[nt][1]; gv = r0; ov = r1; }
            float ig = sigm(iv), fg = sigm(fv), gg = tanh_acc(gv), og = sigm(ov);
            float c = fg * cst[nt] + ig * gg;
            cst[nt] = c;
            hv[nt] = og * tanh_acc(c);
        }

        if (t < TT - 1) {
            hx_s[lrow * 16 + lcol[0]] = hv[0];
            hx_s[lrow * 16 + lcol[1]] = hv[1];
            __syncthreads();
            if (tid < 64) {
                int row = tid >> 1, part = tid & 1;
                const float* s = hx_s + row * 16 + part * 8;
                __half2 h0 = __floats2half2_rn(s[0], s[1]);
                __half2 h1 = __floats2half2_rn(s[2], s[3]);
                __half2 h2 = __floats2half2_rn(s[4], s[5]);
                __half2 h3 = __floats2half2_rn(s[6], s[7]);
                uint4 pk;
                pk.x = *(uint32_t*)&h0; pk.y = *(uint32_t*)&h1;
                pk.z = *(uint32_t*)&h2; pk.w = *(uint32_t*)&h3;
                __half* hdst = g_hh + ((t + 1) & 1) * (NB * HH)
                             + (nBase + row) * HH + j0 + part * 8;
                __stcg((uint4*)hdst, pk);
            }
            __syncthreads();
            if (tid == 0) red_rel(bar, 1u);
        } else {
            out[myrow * HH + j0 + lcol[0]] = hv[0];
            out[myrow * HH + j0 + lcol[1]] = hv[1];
            if (out_n >= 2 * NB * HH) {
                out[NB * HH + myrow * HH + j0 + lcol[0]] = cst[0];
                out[NB * HH + myrow * HH + j0 + lcol[1]] = cst[1];
            }
        }
    }
}

// ================= launch ==================================================
extern "C" void kernel_launch(void* const* d_in, const int* in_sizes, int n_in,
                              void* d_out, int out_size) {
    const float* x    = (const float*)d_in[0];
    const float* w_ii = (const float*)d_in[1];
    const float* w_hi = (const float*)d_in[2];
    const float* w_if = (const float*)d_in[3];
    const float* w_hf = (const float*)d_in[4];
    const float* w_ig = (const float*)d_in[5];
    const float* w_hg = (const float*)d_in[6];
    const float* w_io = (const float*)d_in[7];
    const float* w_ho = (const float*)d_in[8];
    const float* b_ii = (const float*)d_in[9];
    const float* b_hi = (const float*)d_in[10];
    const float* b_if = (const float*)d_in[11];
    const float* b_hf = (const float*)d_in[12];
    const float* b_ig = (const float*)d_in[13];
    const float* b_hg = (const float*)d_in[14];
    const float* b_io = (const float*)d_in[15];
    const float* b_ho = (const float*)d_in[16];
    float* out = (float*)d_out;

    void* barAddr = nullptr;
    cudaGetSymbolAddress(&barAddr, g_bars);
    cudaMemsetAsync(barAddr, 0, 8 * 32 * sizeof(unsigned), 0);

    prep_w<<<2048, 256>>>(w_ii, w_if, w_ig, w_io, w_hi, w_hf, w_hg, w_ho);
    prep_b<<<4, 256>>>(b_ii, b_hi, b_if, b_hf, b_ig, b_hg, b_io, b_ho);
    prep_x<<<(NB * TT * 256 / 4) / 256, 256>>>(x);

    static int smem_set = 0;
    if (!smem_set) {
        cudaFuncSetAttribute(lstm_xw_kernel,
                             cudaFuncAttributeMaxDynamicSharedMemorySize, P1_SMEM);
        smem_set = 1;
    }
    dim3 g1(8, 512);
    lstm_xw_kernel<<<g1, 256, P1_SMEM>>>();

    lstm_rec_kernel<<<128, 256>>>(out, out_size);
}

// round 10
// speedup vs baseline: 1.4445x; 1.2103x over previous
#include <cuda_runtime.h>
#include <cuda_fp16.h>
#include <stdint.h>

#define TT 512
#define NB 256
#define HH 256
#define GG 1024

// vcol = jj*4 + gate  (jj = hidden col; gate: 0=i 1=f 2=g 3=o)
__device__ __half   g_xh[(size_t)NB * TT * 256];  // x in fp16 [n][t][d]
__device__ __half   g_hh[2 * NB * HH];            // fp16 hidden, double buffered
__device__ __half   g_wtx[1024 * 256];            // [vcol][k] Wx fp16
__device__ __half   g_wth[1024 * 256];            // [vcol][k] Wh fp16
__device__ float    g_bvc[1024];                  // combined bias per vcol
__device__ unsigned g_bars[8 * 32];

__device__ __forceinline__ void mma16(float d[4], uint32_t a0, uint32_t a1,
                                      uint32_t a2, uint32_t a3, uint32_t b0, uint32_t b1) {
    asm volatile("mma.sync.aligned.m16n8k16.row.col.f32.f16.f16.f32 "
                 "{%0,%1,%2,%3}, {%4,%5,%6,%7}, {%8,%9}, {%0,%1,%2,%3};\n"
                 : "+f"(d[0]), "+f"(d[1]), "+f"(d[2]), "+f"(d[3])
                 : "r"(a0), "r"(a1), "r"(a2), "r"(a3), "r"(b0), "r"(b1));
}
__device__ __forceinline__ float sigm(float x) { return __fdividef(1.f, 1.f + __expf(-x)); }
__device__ __forceinline__ float tanh_acc(float x) { return 1.f - __fdividef(2.f, __expf(2.f * x) + 1.f); }
__device__ __forceinline__ unsigned ld_acq(const unsigned* p) {
    unsigned v; asm volatile("ld.acquire.gpu.global.u32 %0, [%1];" : "=r"(v) : "l"(p)); return v;
}
__device__ __forceinline__ void red_rel(unsigned* p, unsigned v) {
    asm volatile("red.release.gpu.global.add.u32 [%0], %1;" :: "l"(p), "r"(v) : "memory");
}
__device__ __forceinline__ uint32_t smem_u32(const void* p) {
    return (uint32_t)__cvta_generic_to_shared(p);
}
__device__ __forceinline__ void ldsm4(uint32_t& a0, uint32_t& a1, uint32_t& a2,
                                      uint32_t& a3, uint32_t addr) {
    asm volatile("ldmatrix.sync.aligned.m8n8.x4.shared.b16 {%0,%1,%2,%3}, [%4];"
                 : "=r"(a0), "=r"(a1), "=r"(a2), "=r"(a3) : "r"(addr));
}

// ============ Prep kernels ================================================
__global__ void prep_w(const float* __restrict__ xi, const float* __restrict__ xf,
                       const float* __restrict__ xg, const float* __restrict__ xo,
                       const float* __restrict__ hi, const float* __restrict__ hf,
                       const float* __restrict__ hg, const float* __restrict__ ho) {
    int which = blockIdx.x >> 10, vv = blockIdx.x & 1023;
    int jj = vv >> 2, gt = vv & 3, k = threadIdx.x;
    const float* w;
    if (which == 0) w = (gt == 0) ? xi : (gt == 1) ? xf : (gt == 2) ? xg : xo;
    else            w = (gt == 0) ? hi : (gt == 1) ? hf : (gt == 2) ? hg : ho;
    __half* dst = which == 0 ? g_wtx : g_wth;
    dst[((size_t)vv << 8) + k] = __float2half_rn(w[k * 256 + jj]);
}
__global__ void prep_b(const float* __restrict__ b0, const float* __restrict__ b1,
                       const float* __restrict__ b2, const float* __restrict__ b3,
                       const float* __restrict__ b4, const float* __restrict__ b5,
                       const float* __restrict__ b6, const float* __restrict__ b7) {
    int vv = blockIdx.x * 256 + threadIdx.x;
    int jj = vv >> 2, gt = vv & 3;
    const float* bx = (gt == 0) ? b0 : (gt == 1) ? b2 : (gt == 2) ? b4 : b6;
    const float* bh = (gt == 0) ? b1 : (gt == 1) ? b3 : (gt == 2) ? b5 : b7;
    g_bvc[vv] = bx[jj] + bh[jj];
}
__global__ void prep_x(const float* __restrict__ x) {
    size_t i = ((size_t)blockIdx.x * 256 + threadIdx.x);
    float4 v = *(const float4*)(x + i * 4);
    __half2 h0 = __floats2half2_rn(v.x, v.y);
    __half2 h1 = __floats2half2_rn(v.z, v.w);
    uint2 pk; pk.x = *(uint32_t*)&h0; pk.y = *(uint32_t*)&h1;
    *(uint2*)(g_xh + i * 4) = pk;
}

// ================= Fused persistent LSTM ===================================
// 128 CTAs: bn=blk>>4 (32-row batch group), bj=blk&15 (16 hidden cols = 64
// vcols). 8 warps: wm=warp&1 (row half), wc=warp>>1. Warp: 16 rows x 16 vcols.
// Per step: acc=bias; x(t)-mma (pre-barrier, fills the wait window);
// barrier; stage h(t) + x(t+1); h(t)-mma; cell update; h out via smem bounce.
// Wx AND Wh fragments live in registers for the whole run.
#define HSH 264

__global__ void __launch_bounds__(256, 1) lstm_rec_kernel(
    float* __restrict__ out, int out_n)
{
    __shared__ __align__(16) __half h_s[32 * HSH];
    __shared__ __align__(16) __half x_s[32 * HSH];
    __shared__ __align__(16) float  hx_s[32 * 16];

    const int tid = threadIdx.x, lane = tid & 31, warp = tid >> 5;
    const int wm = warp & 1, wc = warp >> 1;
    const int bn = blockIdx.x >> 4, bj = blockIdx.x & 15;
    const int nBase = bn * 32, j0 = bj * 16;
    const int u = lane >> 2, r = lane & 3;
    const int rA = wm * 16 + u;

    unsigned* bar = &g_bars[bn * 32];

    // ---- persistent B fragments: Wh and Wx (vcol-contiguous rows) ----
    uint32_t hb0[16][2], hb1[16][2], xb0[16][2], xb1[16][2];
    #pragma unroll
    for (int nt = 0; nt < 2; nt++) {
        const size_t vrow = (size_t)(bj * 64 + wc * 16 + nt * 8 + u) * 256;
        const __half* wph = g_wth + vrow;
        const __half* wpx = g_wtx + vrow;
        #pragma unroll
        for (int kc = 0; kc < 16; kc++) {
            hb0[kc][nt] = *(const uint32_t*)(wph + kc * 16 + 2 * r);
            hb1[kc][nt] = *(const uint32_t*)(wph + kc * 16 + 2 * r + 8);
            xb0[kc][nt] = *(const uint32_t*)(wpx + kc * 16 + 2 * r);
            xb1[kc][nt] = *(const uint32_t*)(wpx + kc * 16 + 2 * r + 8);
        }
    }

    // bias per accumulator column
    float biasA[2], biasB[2];
    #pragma unroll
    for (int nt = 0; nt < 2; nt++) {
        int vc = bj * 64 + wc * 16 + nt * 8 + 2 * r;
        biasA[nt] = g_bvc[vc];
        biasB[nt] = g_bvc[vc + 1];
    }

    // ldmatrix A base addresses
    const int matrow = (lane & 7) + ((lane >> 3) & 1) * 8;
    const int colh   = (lane >> 4) * 8;
    const uint32_t habase = smem_u32(h_s) + ((wm * 16 + matrow) * HSH + colh) * 2;
    const uint32_t xabase = smem_u32(x_s) + ((wm * 16 + matrow) * HSH + colh) * 2;

    const int odd = lane & 1;
    const int lrow = rA + (odd ? 8 : 0);
    const int myrow = nBase + lrow;
    int lcol[2];
    #pragma unroll
    for (int nt = 0; nt < 2; nt++) lcol[nt] = wc * 4 + nt * 2 + (r >> 1);

    // x staging coords (4 x 16B per thread)
    int xrow[4], xc8[4];
    #pragma unroll
    for (int i = 0; i < 4; i++) {
        int f = i * 256 + tid;
        xrow[i] = f >> 5; xc8[i] = (f & 31) << 3;
    }

    float cst[2] = {0.f, 0.f};

    // prime: stage x(0)
    #pragma unroll
    for (int i = 0; i < 4; i++) {
        const __half* src = g_xh + ((size_t)(nBase + xrow[i]) * TT) * 256 + xc8[i];
        uint4 v = __ldg((const uint4*)src);
        *(uint4*)(x_s + xrow[i] * HSH + xc8[i]) = v;
    }
    __syncthreads();

    for (int t = 0; t < TT; t++) {
        // prefetch x(t+1) into regs (independent of everything)
        uint4 xr[4];
        if (t + 1 < TT) {
            #pragma unroll
            for (int i = 0; i < 4; i++) {
                const __half* src = g_xh
                    + ((size_t)(nBase + xrow[i]) * TT + (t + 1)) * 256 + xc8[i];
                xr[i] = __ldg((const uint4*)src);
            }
        }

        // acc = bias; x-mma (split-K) BEFORE barrier — fills wait window
        float acc[2][4], acb[2][4];
        #pragma unroll
        for (int nt = 0; nt < 2; nt++) {
            acc[nt][0] = biasA[nt]; acc[nt][1] = biasB[nt];
            acc[nt][2] = biasA[nt]; acc[nt][3] = biasB[nt];
            acb[nt][0] = 0.f; acb[nt][1] = 0.f; acb[nt][2] = 0.f; acb[nt][3] = 0.f;
        }
        #pragma unroll
        for (int kc = 0; kc < 8; kc++) {
            uint32_t a0, a1, a2, a3, c0, c1, c2, c3;
            ldsm4(a0, a1, a2, a3, xabase + kc * 32);
            ldsm4(c0, c1, c2, c3, xabase + (kc + 8) * 32);
            mma16(acc[0], a0, a1, a2, a3, xb0[kc][0], xb1[kc][0]);
            mma16(acc[1], a0, a1, a2, a3, xb0[kc][1], xb1[kc][1]);
            mma16(acb[0], c0, c1, c2, c3, xb0[kc + 8][0], xb1[kc + 8][0]);
            mma16(acb[1], c0, c1, c2, c3, xb0[kc + 8][1], xb1[kc + 8][1]);
        }

        if (t > 0) {
            if (tid == 0) {
                unsigned target = 16u * (unsigned)t;
                while (ld_acq(bar) < target) { }
            }
        }
        __syncthreads();   // all warps past x-mma (x_s free) + barrier observed

        // stage h(t) (if any) and x(t+1)
        if (t > 0) {
            const __half* hsrc = g_hh + (t & 1) * (NB * HH) + nBase * HH;
            #pragma unroll
            for (int i = 0; i < 4; i++) {
                int f = i * 256 + tid, row = f >> 5, c8 = (f & 31) << 3;
                uint4 v = __ldcg((const uint4*)(hsrc + row * HH + c8));
                *(uint4*)(h_s + row * HSH + c8) = v;
            }
        }
        if (t + 1 < TT) {
            #pragma unroll
            for (int i = 0; i < 4; i++)
                *(uint4*)(x_s + xrow[i] * HSH + xc8[i]) = xr[i];
        }
        __syncthreads();

        if (t > 0) {
            #pragma unroll
            for (int kc = 0; kc < 8; kc++) {
                uint32_t a0, a1, a2, a3, c0, c1, c2, c3;
                ldsm4(a0, a1, a2, a3, habase + kc * 32);
                ldsm4(c0, c1, c2, c3, habase + (kc + 8) * 32);
                mma16(acc[0], a0, a1, a2, a3, hb0[kc][0], hb1[kc][0]);
                mma16(acc[1], a0, a1, a2, a3, hb0[kc][1], hb1[kc][1]);
                mma16(acb[0], c0, c1, c2, c3, hb0[kc + 8][0], hb1[kc + 8][0]);
                mma16(acb[1], c0, c1, c2, c3, hb0[kc + 8][1], hb1[kc + 8][1]);
            }
        }
        #pragma unroll
        for (int nt = 0; nt < 2; nt++)
            #pragma unroll
            for (int j = 0; j < 4; j++) acc[nt][j] += acb[nt][j];

        // cell update (lane-pair gate exchange)
        float hv[2];
        #pragma unroll
        for (int nt = 0; nt < 2; nt++) {
            float s0 = odd ? acc[nt][0] : acc[nt][2];
            float s1 = odd ? acc[nt][1] : acc[nt][3];
            float r0 = __shfl_xor_sync(0xFFFFFFFFu, s0, 1);
            float r1 = __shfl_xor_sync(0xFFFFFFFFu, s1, 1);
            float iv, fv, gv, ov;
            if (odd) { iv = r0; fv = r1; gv = acc[nt][2]; ov = acc[nt][3]; }
            else     { iv = acc[nt][0]; fv = acc[nt][1]; gv = r0; ov = r1; }
            float ig = sigm(iv), fg = sigm(fv), gg = tanh_acc(gv), og = sigm(ov);
            float c = fg * cst[nt] + ig * gg;
            cst[nt] = c;
            hv[nt] = og * tanh_acc(c);
        }

        if (t < TT - 1) {
            hx_s[lrow * 16 + lcol[0]] = hv[0];
            hx_s[lrow * 16 + lcol[1]] = hv[1];
            __syncthreads();
            if (tid < 64) {
                int row = tid >> 1, part = tid & 1;
                const float* s = hx_s + row * 16 + part * 8;
                __half2 h0 = __floats2half2_rn(s[0], s[1]);
                __half2 h1 = __floats2half2_rn(s[2], s[3]);
                __half2 h2 = __floats2half2_rn(s[4], s[5]);
                __half2 h3 = __floats2half2_rn(s[6], s[7]);
                uint4 pk;
                pk.x = *(uint32_t*)&h0; pk.y = *(uint32_t*)&h1;
                pk.z = *(uint32_t*)&h2; pk.w = *(uint32_t*)&h3;
                __half* hdst = g_hh + ((t + 1) & 1) * (NB * HH)
                             + (nBase + row) * HH + j0 + part * 8;
                __stcg((uint4*)hdst, pk);
            }
            __syncthreads();
            if (tid == 0) red_rel(bar, 1u);
        } else {
            out[myrow * HH + j0 + lcol[0]] = hv[0];
            out[myrow * HH + j0 + lcol[1]] = hv[1];
            if (out_n >= 2 * NB * HH) {
                out[NB * HH + myrow * HH + j0 + lcol[0]] = cst[0];
                out[NB * HH + myrow * HH + j0 + lcol[1]] = cst[1];
            }
        }
    }
}

// ================= launch ==================================================
extern "C" void kernel_launch(void* const* d_in, const int* in_sizes, int n_in,
                              void* d_out, int out_size) {
    const float* x    = (const float*)d_in[0];
    const float* w_ii = (const float*)d_in[1];
    const float* w_hi = (const float*)d_in[2];
    const float* w_if = (const float*)d_in[3];
    const float* w_hf = (const float*)d_in[4];
    const float* w_ig = (const float*)d_in[5];
    const float* w_hg = (const float*)d_in[6];
    const float* w_io = (const float*)d_in[7];
    const float* w_ho = (const float*)d_in[8];
    const float* b_ii = (const float*)d_in[9];
    const float* b_hi = (const float*)d_in[10];
    const float* b_if = (const float*)d_in[11];
    const float* b_hf = (const float*)d_in[12];
    const float* b_ig = (const float*)d_in[13];
    const float* b_hg = (const float*)d_in[14];
    const float* b_io = (const float*)d_in[15];
    const float* b_ho = (const float*)d_in[16];
    float* out = (float*)d_out;

    void* barAddr = nullptr;
    cudaGetSymbolAddress(&barAddr, g_bars);
    cudaMemsetAsync(barAddr, 0, 8 * 32 * sizeof(unsigned), 0);

    prep_w<<<2048, 256>>>(w_ii, w_if, w_ig, w_io, w_hi, w_hf, w_hg, w_ho);
    prep_b<<<4, 256>>>(b_ii, b_hi, b_if, b_hf, b_ig, b_hg, b_io, b_ho);
    prep_x<<<(NB * TT * 256 / 4) / 256, 256>>>(x);

    lstm_rec_kernel<<<128, 256>>>(out, out_size);
}